// round 1
// baseline (speedup 1.0000x reference)
#include <cuda_runtime.h>
#include <math.h>

#define TT 6
#define NN 50000
#define EE 800000
#define FF 32
#define HH 64
#define GG 192          // 3 gates * H
#define OUTC 16

// ---------------- scratch (device globals; no allocation allowed) ----------
__device__ __align__(16) float g_xw [(size_t)NN * GG];   // projected features, 3 gates fused
__device__ __align__(16) float g_agg[(size_t)NN * GG];   // GCN aggregation accumulator
__device__ __align__(16) float g_h  [(size_t)NN * HH];   // GRU hidden state
__device__ int   g_deg [NN];
__device__ float g_dinv[NN];

// ---------------- small helpers -------------------------------------------
__device__ __forceinline__ float sigmoidf_(float x) {
    return 1.0f / (1.0f + __expf(-x));
}

// warp-collective 128x64 matvec: rows 0..63 carry (v0,v1) distributed across
// lanes, rows 64..127 carry (u0,u1). Lane computes output cols lane, lane+32.
__device__ __forceinline__ void matvec128(const float* __restrict__ W,
                                          float v0, float v1, float u0, float u1,
                                          int j0, int j1, float& o0, float& o1) {
    float a0 = 0.f, a1 = 0.f;
    #pragma unroll 8
    for (int k = 0; k < 32; k++) {
        float a = __shfl_sync(0xffffffffu, v0, k);
        a0 += a * __ldg(W + k * 64 + j0);
        a1 += a * __ldg(W + k * 64 + j1);
    }
    #pragma unroll 8
    for (int k = 0; k < 32; k++) {
        float a = __shfl_sync(0xffffffffu, v1, k);
        a0 += a * __ldg(W + (32 + k) * 64 + j0);
        a1 += a * __ldg(W + (32 + k) * 64 + j1);
    }
    #pragma unroll 8
    for (int k = 0; k < 32; k++) {
        float a = __shfl_sync(0xffffffffu, u0, k);
        a0 += a * __ldg(W + (64 + k) * 64 + j0);
        a1 += a * __ldg(W + (64 + k) * 64 + j1);
    }
    #pragma unroll 8
    for (int k = 0; k < 32; k++) {
        float a = __shfl_sync(0xffffffffu, u1, k);
        a0 += a * __ldg(W + (96 + k) * 64 + j0);
        a1 += a * __ldg(W + (96 + k) * 64 + j1);
    }
    o0 = a0; o1 = a1;
}

// ---------------- kernels ---------------------------------------------------

__global__ void k_clear_h() {
    unsigned idx = blockIdx.x * blockDim.x + threadIdx.x;
    if (idx < (unsigned)(NN * HH)) g_h[idx] = 0.0f;
}

__global__ void k_clear_deg() {
    unsigned i = blockIdx.x * blockDim.x + threadIdx.x;
    if (i < (unsigned)NN) g_deg[i] = 0;
}

__global__ void k_deg(const int* __restrict__ dst) {
    unsigned e = blockIdx.x * blockDim.x + threadIdx.x;
    if (e < (unsigned)EE) atomicAdd(&g_deg[__ldg(dst + e)], 1);
}

// warp-per-node: xw[i,:] = x[i,:] @ [Wz|Wr|Wh]; agg[i,:] = xw[i,:] * dinv[i]^2
// (self-loop contribution), also finalizes dinv[i].
__global__ void k_proj_self(const float* __restrict__ x,
                            const float* __restrict__ Wz,
                            const float* __restrict__ Wr,
                            const float* __restrict__ Wh) {
    __shared__ float Wc[FF][GG];   // 24 KB
    int tid = threadIdx.x;
    for (int idx = tid; idx < FF * GG; idx += blockDim.x) {
        int k = idx / GG, j = idx - k * GG;
        float w;
        if (j < HH)            w = Wz[k * HH + j];
        else if (j < 2 * HH)   w = Wr[k * HH + (j - HH)];
        else                   w = Wh[k * HH + (j - 2 * HH)];
        Wc[k][j] = w;
    }
    __syncthreads();

    int warp = tid >> 5, lane = tid & 31;
    int i = blockIdx.x * (blockDim.x >> 5) + warp;
    if (i >= NN) return;

    float xv = __ldg(x + (size_t)i * FF + lane);   // lane k holds x[i][k]
    float di = 0.0f;
    if (lane == 0) {
        di = rsqrtf((float)(g_deg[i] + 1));        // +1 self-loop
        g_dinv[i] = di;
    }
    di = __shfl_sync(0xffffffffu, di, 0);

    float acc[6] = {0.f, 0.f, 0.f, 0.f, 0.f, 0.f};
    #pragma unroll
    for (int k = 0; k < FF; k++) {
        float a = __shfl_sync(0xffffffffu, xv, k);
        #pragma unroll
        for (int c = 0; c < 6; c++) acc[c] += a * Wc[k][lane + 32 * c];
    }
    float dd = di * di;
    size_t base = (size_t)i * GG + lane;
    #pragma unroll
    for (int c = 0; c < 6; c++) {
        g_xw [base + 32 * c] = acc[c];
        g_agg[base + 32 * c] = acc[c] * dd;
    }
}

// one thread per (edge, 16B-chunk): 48 chunks cover 192 floats (3 gates).
__global__ void k_scatter(const int* __restrict__ src, const int* __restrict__ dst) {
    unsigned idx = blockIdx.x * blockDim.x + threadIdx.x;
    if (idx >= (unsigned)EE * 48u) return;
    unsigned e = idx / 48u;
    unsigned c = idx - e * 48u;
    int s = __ldg(src + e);
    int d = __ldg(dst + e);
    float nrm = __ldg(&g_dinv[s]) * __ldg(&g_dinv[d]);
    const float4* xr = reinterpret_cast<const float4*>(g_xw + (size_t)s * GG);
    float4 v = __ldg(xr + c);
    v.x *= nrm; v.y *= nrm; v.z *= nrm; v.w *= nrm;
    float4* ap = reinterpret_cast<float4*>(g_agg + (size_t)d * GG) + c;
    asm volatile("red.global.add.v4.f32 [%0], {%1,%2,%3,%4};"
                 :: "l"(ap), "f"(v.x), "f"(v.y), "f"(v.z), "f"(v.w) : "memory");
}

// warp-per-node GRU gate update.
__global__ void k_gates(const float* __restrict__ bz, const float* __restrict__ br,
                        const float* __restrict__ bh,
                        const float* __restrict__ Lz, const float* __restrict__ Lzb,
                        const float* __restrict__ Lr, const float* __restrict__ Lrb,
                        const float* __restrict__ Lh, const float* __restrict__ Lhb) {
    int warp = threadIdx.x >> 5, lane = threadIdx.x & 31;
    int i = blockIdx.x * (blockDim.x >> 5) + warp;
    if (i >= NN) return;

    const float* ag = g_agg + (size_t)i * GG;
    float gz0 = ag[lane]       + __ldg(bz + lane);
    float gz1 = ag[lane + 32]  + __ldg(bz + lane + 32);
    float gr0 = ag[64 + lane]      + __ldg(br + lane);
    float gr1 = ag[64 + lane + 32] + __ldg(br + lane + 32);
    float gh0 = ag[128 + lane]      + __ldg(bh + lane);
    float gh1 = ag[128 + lane + 32] + __ldg(bh + lane + 32);

    size_t hb = (size_t)i * HH;
    float h0 = g_h[hb + lane];
    float h1 = g_h[hb + lane + 32];
    int j0 = lane, j1 = lane + 32;

    float z0, z1;
    matvec128(Lz, gz0, gz1, h0, h1, j0, j1, z0, z1);
    float Z0 = sigmoidf_(z0 + __ldg(Lzb + j0));
    float Z1 = sigmoidf_(z1 + __ldg(Lzb + j1));

    float r0, r1;
    matvec128(Lr, gr0, gr1, h0, h1, j0, j1, r0, r1);
    float R0 = sigmoidf_(r0 + __ldg(Lrb + j0));
    float R1 = sigmoidf_(r1 + __ldg(Lrb + j1));

    float hr0 = h0 * R0, hr1 = h1 * R1;
    float t0, t1;
    matvec128(Lh, gh0, gh1, hr0, hr1, j0, j1, t0, t1);
    float Ht0 = tanhf(t0 + __ldg(Lhb + j0));
    float Ht1 = tanhf(t1 + __ldg(Lhb + j1));

    g_h[hb + lane]      = Z0 * h0 + (1.0f - Z0) * Ht0;
    g_h[hb + lane + 32] = Z1 * h1 + (1.0f - Z1) * Ht1;
}

__global__ void k_out(const float* __restrict__ oW, const float* __restrict__ ob,
                      float* __restrict__ out) {
    unsigned idx = blockIdx.x * blockDim.x + threadIdx.x;
    if (idx >= (unsigned)(NN * OUTC)) return;
    int i = idx >> 4, j = idx & 15;
    const float* hr = g_h + (size_t)i * HH;
    float acc = __ldg(ob + j);
    #pragma unroll
    for (int k = 0; k < HH; k++) acc += hr[k] * __ldg(oW + k * OUTC + j);
    out[idx] = acc;
}

// ---------------- launch ----------------------------------------------------
extern "C" void kernel_launch(void* const* d_in, const int* in_sizes, int n_in,
                              void* d_out, int out_size) {
    const float* xs  = (const float*)d_in[0];
    const int*   ei  = (const int*)  d_in[1];
    const float* Wz  = (const float*)d_in[2];
    const float* bz  = (const float*)d_in[3];
    const float* Wr  = (const float*)d_in[4];
    const float* br  = (const float*)d_in[5];
    const float* Wh  = (const float*)d_in[6];
    const float* bh  = (const float*)d_in[7];
    const float* Lz  = (const float*)d_in[8];
    const float* Lzb = (const float*)d_in[9];
    const float* Lr  = (const float*)d_in[10];
    const float* Lrb = (const float*)d_in[11];
    const float* Lh  = (const float*)d_in[12];
    const float* Lhb = (const float*)d_in[13];
    const float* oW  = (const float*)d_in[14];
    const float* ob  = (const float*)d_in[15];
    float* out = (float*)d_out;

    k_clear_h<<<(NN * HH + 255) / 256, 256>>>();

    for (int t = 0; t < TT; t++) {
        const float* x   = xs + (size_t)t * NN * FF;
        const int*   src = ei + (size_t)t * 2 * EE;
        const int*   dst = src + EE;

        k_clear_deg<<<(NN + 255) / 256, 256>>>();
        k_deg<<<(EE + 255) / 256, 256>>>(dst);
        k_proj_self<<<(NN + 7) / 8, 256>>>(x, Wz, Wr, Wh);
        unsigned total = (unsigned)EE * 48u;
        k_scatter<<<(total + 255) / 256, 256>>>(src, dst);
        k_gates<<<(NN + 7) / 8, 256>>>(bz, br, bh, Lz, Lzb, Lr, Lrb, Lh, Lhb);
    }

    k_out<<<(NN * OUTC + 255) / 256, 256>>>(oW, ob, out);
}

// round 2
// speedup vs baseline: 1.1831x; 1.1831x over previous
#include <cuda_runtime.h>
#include <math.h>

#define TT 6
#define NN 50000
#define EE 800000
#define FF 32
#define HH 64
#define GG 192          // 3 gates * H
#define OUTC 16

// ---------------- scratch (device globals; no allocation allowed) ----------
__device__ __align__(16) float g_aggx[(size_t)NN * FF];  // aggregated raw features (A_hat @ X)
__device__ __align__(16) float g_h   [(size_t)NN * HH];  // GRU hidden state
__device__ int   g_deg [NN];
__device__ float g_dinv[NN];

// ---------------- small helpers -------------------------------------------
__device__ __forceinline__ float sigmoidf_(float x) {
    return 1.0f / (1.0f + __expf(-x));
}

// warp-collective 128x64 matvec: rows 0..63 carry (v0,v1) distributed across
// lanes, rows 64..127 carry (u0,u1). Lane computes output cols lane, lane+32.
__device__ __forceinline__ void matvec128(const float* __restrict__ W,
                                          float v0, float v1, float u0, float u1,
                                          int j0, int j1, float& o0, float& o1) {
    float a0 = 0.f, a1 = 0.f;
    #pragma unroll 8
    for (int k = 0; k < 32; k++) {
        float a = __shfl_sync(0xffffffffu, v0, k);
        a0 += a * __ldg(W + k * 64 + j0);
        a1 += a * __ldg(W + k * 64 + j1);
    }
    #pragma unroll 8
    for (int k = 0; k < 32; k++) {
        float a = __shfl_sync(0xffffffffu, v1, k);
        a0 += a * __ldg(W + (32 + k) * 64 + j0);
        a1 += a * __ldg(W + (32 + k) * 64 + j1);
    }
    #pragma unroll 8
    for (int k = 0; k < 32; k++) {
        float a = __shfl_sync(0xffffffffu, u0, k);
        a0 += a * __ldg(W + (64 + k) * 64 + j0);
        a1 += a * __ldg(W + (64 + k) * 64 + j1);
    }
    #pragma unroll 8
    for (int k = 0; k < 32; k++) {
        float a = __shfl_sync(0xffffffffu, u1, k);
        a0 += a * __ldg(W + (96 + k) * 64 + j0);
        a1 += a * __ldg(W + (96 + k) * 64 + j1);
    }
    o0 = a0; o1 = a1;
}

// ---------------- kernels ---------------------------------------------------

__global__ void k_clear_h() {
    unsigned idx = blockIdx.x * blockDim.x + threadIdx.x;
    if (idx < (unsigned)(NN * HH)) g_h[idx] = 0.0f;
}

__global__ void k_clear_deg() {
    unsigned i = blockIdx.x * blockDim.x + threadIdx.x;
    if (i < (unsigned)NN) g_deg[i] = 0;
}

__global__ void k_deg(const int* __restrict__ dst) {
    unsigned e = blockIdx.x * blockDim.x + threadIdx.x;
    if (e < (unsigned)EE) atomicAdd(&g_deg[__ldg(dst + e)], 1);
}

// thread per (node, float4-chunk of F=32): init aggx with self-loop term
// aggx[i] = x[i] * dinv[i]^2, and store dinv.
__global__ void k_init(const float* __restrict__ x) {
    unsigned idx = blockIdx.x * blockDim.x + threadIdx.x;
    if (idx >= (unsigned)NN * 8u) return;
    unsigned i = idx >> 3, c = idx & 7u;
    float di = rsqrtf((float)(g_deg[i] + 1));
    if (c == 0) g_dinv[i] = di;
    float dd = di * di;
    float4 v = __ldg(reinterpret_cast<const float4*>(x + (size_t)i * FF) + c);
    v.x *= dd; v.y *= dd; v.z *= dd; v.w *= dd;
    reinterpret_cast<float4*>(g_aggx + (size_t)i * FF)[c] = v;
}

// one thread per (edge, float4-chunk): 8 chunks cover 32 raw features.
__global__ void k_scatter(const float* __restrict__ x,
                          const int* __restrict__ src, const int* __restrict__ dst) {
    unsigned idx = blockIdx.x * blockDim.x + threadIdx.x;
    if (idx >= (unsigned)EE * 8u) return;
    unsigned e = idx >> 3;
    unsigned c = idx & 7u;
    int s = __ldg(src + e);
    int d = __ldg(dst + e);
    float nrm = __ldg(&g_dinv[s]) * __ldg(&g_dinv[d]);
    float4 v = __ldg(reinterpret_cast<const float4*>(x + (size_t)s * FF) + c);
    v.x *= nrm; v.y *= nrm; v.z *= nrm; v.w *= nrm;
    float4* ap = reinterpret_cast<float4*>(g_aggx + (size_t)d * FF) + c;
    asm volatile("red.global.add.v4.f32 [%0], {%1,%2,%3,%4};"
                 :: "l"(ap), "f"(v.x), "f"(v.y), "f"(v.z), "f"(v.w) : "memory");
}

// warp-per-node: project aggx[i,:] @ [Wz|Wr|Wh] (+biases), then GRU update.
__global__ void k_proj_gates(const float* __restrict__ Wz, const float* __restrict__ bz,
                             const float* __restrict__ Wr, const float* __restrict__ br,
                             const float* __restrict__ Wh, const float* __restrict__ bh,
                             const float* __restrict__ Lz, const float* __restrict__ Lzb,
                             const float* __restrict__ Lr, const float* __restrict__ Lrb,
                             const float* __restrict__ Lh, const float* __restrict__ Lhb) {
    __shared__ float Wc[FF][GG];   // 24 KB: [Wz|Wr|Wh] column-fused
    int tid = threadIdx.x;
    for (int idx = tid; idx < FF * GG; idx += blockDim.x) {
        int k = idx / GG, j = idx - k * GG;
        float w;
        if (j < HH)            w = Wz[k * HH + j];
        else if (j < 2 * HH)   w = Wr[k * HH + (j - HH)];
        else                   w = Wh[k * HH + (j - 2 * HH)];
        Wc[k][j] = w;
    }
    __syncthreads();

    int warp = tid >> 5, lane = tid & 31;
    int i = blockIdx.x * (blockDim.x >> 5) + warp;
    if (i >= NN) return;

    // lane k holds aggx[i][k]
    float av = g_aggx[(size_t)i * FF + lane];

    float acc[6] = {0.f, 0.f, 0.f, 0.f, 0.f, 0.f};
    #pragma unroll
    for (int k = 0; k < FF; k++) {
        float a = __shfl_sync(0xffffffffu, av, k);
        #pragma unroll
        for (int c = 0; c < 6; c++) acc[c] += a * Wc[k][lane + 32 * c];
    }

    // gate pre-activations (GCN outputs + biases)
    float gz0 = acc[0] + __ldg(bz + lane);
    float gz1 = acc[1] + __ldg(bz + lane + 32);
    float gr0 = acc[2] + __ldg(br + lane);
    float gr1 = acc[3] + __ldg(br + lane + 32);
    float gh0 = acc[4] + __ldg(bh + lane);
    float gh1 = acc[5] + __ldg(bh + lane + 32);

    size_t hb = (size_t)i * HH;
    float h0 = g_h[hb + lane];
    float h1 = g_h[hb + lane + 32];
    int j0 = lane, j1 = lane + 32;

    float z0, z1;
    matvec128(Lz, gz0, gz1, h0, h1, j0, j1, z0, z1);
    float Z0 = sigmoidf_(z0 + __ldg(Lzb + j0));
    float Z1 = sigmoidf_(z1 + __ldg(Lzb + j1));

    float r0, r1;
    matvec128(Lr, gr0, gr1, h0, h1, j0, j1, r0, r1);
    float R0 = sigmoidf_(r0 + __ldg(Lrb + j0));
    float R1 = sigmoidf_(r1 + __ldg(Lrb + j1));

    float hr0 = h0 * R0, hr1 = h1 * R1;
    float t0, t1;
    matvec128(Lh, gh0, gh1, hr0, hr1, j0, j1, t0, t1);
    float Ht0 = tanhf(t0 + __ldg(Lhb + j0));
    float Ht1 = tanhf(t1 + __ldg(Lhb + j1));

    g_h[hb + lane]      = Z0 * h0 + (1.0f - Z0) * Ht0;
    g_h[hb + lane + 32] = Z1 * h1 + (1.0f - Z1) * Ht1;
}

__global__ void k_out(const float* __restrict__ oW, const float* __restrict__ ob,
                      float* __restrict__ out) {
    unsigned idx = blockIdx.x * blockDim.x + threadIdx.x;
    if (idx >= (unsigned)(NN * OUTC)) return;
    int i = idx >> 4, j = idx & 15;
    const float* hr = g_h + (size_t)i * HH;
    float acc = __ldg(ob + j);
    #pragma unroll
    for (int k = 0; k < HH; k++) acc += hr[k] * __ldg(oW + k * OUTC + j);
    out[idx] = acc;
}

// ---------------- launch ----------------------------------------------------
extern "C" void kernel_launch(void* const* d_in, const int* in_sizes, int n_in,
                              void* d_out, int out_size) {
    const float* xs  = (const float*)d_in[0];
    const int*   ei  = (const int*)  d_in[1];
    const float* Wz  = (const float*)d_in[2];
    const float* bz  = (const float*)d_in[3];
    const float* Wr  = (const float*)d_in[4];
    const float* br  = (const float*)d_in[5];
    const float* Wh  = (const float*)d_in[6];
    const float* bh  = (const float*)d_in[7];
    const float* Lz  = (const float*)d_in[8];
    const float* Lzb = (const float*)d_in[9];
    const float* Lr  = (const float*)d_in[10];
    const float* Lrb = (const float*)d_in[11];
    const float* Lh  = (const float*)d_in[12];
    const float* Lhb = (const float*)d_in[13];
    const float* oW  = (const float*)d_in[14];
    const float* ob  = (const float*)d_in[15];
    float* out = (float*)d_out;

    k_clear_h<<<(NN * HH + 255) / 256, 256>>>();

    for (int t = 0; t < TT; t++) {
        const float* x   = xs + (size_t)t * NN * FF;
        const int*   src = ei + (size_t)t * 2 * EE;
        const int*   dst = src + EE;

        k_clear_deg<<<(NN + 255) / 256, 256>>>();
        k_deg<<<(EE + 255) / 256, 256>>>(dst);
        k_init<<<(NN * 8 + 255) / 256, 256>>>(x);
        k_scatter<<<((unsigned)EE * 8u + 255) / 256, 256>>>(x, src, dst);
        k_proj_gates<<<(NN + 7) / 8, 256>>>(Wz, bz, Wr, br, Wh, bh,
                                            Lz, Lzb, Lr, Lrb, Lh, Lhb);
    }

    k_out<<<(NN * OUTC + 255) / 256, 256>>>(oW, ob, out);
}

// round 3
// speedup vs baseline: 2.3107x; 1.9531x over previous
#include <cuda_runtime.h>
#include <math.h>

#define TT 6
#define NN 50000
#define EE 800000
#define FF 32
#define HH 64
#define OUTC 16
#define SPAD 68   // shared k-major stride (16B-aligned rows)

// ---------------- scratch (device globals; no allocation allowed) ----------
__device__ __align__(16) float g_aggx[(size_t)NN * FF];  // A_hat @ X
__device__ __align__(16) float g_h   [(size_t)NN * HH];  // GRU hidden state
__device__ int   g_deg [NN];
__device__ float g_dinv[NN];

// folded / transposed weights (computed once per launch by k_prep)
__device__ __align__(16) float g_Mt [3][HH][FF];  // (W @ L_top)^T : [gate][j][f]
__device__ __align__(16) float g_Lbt[3][HH][HH];  // L_bot^T       : [gate][j][k]
__device__ float g_bv[3][HH];                      // b @ L_top + Lb

__device__ __forceinline__ float sigmoidf_(float x) {
    return 1.0f / (1.0f + __expf(-x));
}

// ---------------- kernels ---------------------------------------------------

__global__ void k_clear_h() {
    unsigned idx = blockIdx.x * blockDim.x + threadIdx.x;
    if (idx < (unsigned)(NN * HH)) g_h[idx] = 0.0f;
}

__global__ void k_clear_deg() {
    unsigned i = blockIdx.x * blockDim.x + threadIdx.x;
    if (i < (unsigned)NN) g_deg[i] = 0;
}

__global__ void k_deg(const int* __restrict__ dst) {
    unsigned e = blockIdx.x * blockDim.x + threadIdx.x;
    if (e < (unsigned)EE) atomicAdd(&g_deg[__ldg(dst + e)], 1);
}

// thread per (node, float4-chunk of F=32): aggx[i] = x[i] * dinv[i]^2 (self loop)
__global__ void k_init(const float* __restrict__ x) {
    unsigned idx = blockIdx.x * blockDim.x + threadIdx.x;
    if (idx >= (unsigned)NN * 8u) return;
    unsigned i = idx >> 3, c = idx & 7u;
    float di = rsqrtf((float)(g_deg[i] + 1));
    if (c == 0) g_dinv[i] = di;
    float dd = di * di;
    float4 v = __ldg(reinterpret_cast<const float4*>(x + (size_t)i * FF) + c);
    v.x *= dd; v.y *= dd; v.z *= dd; v.w *= dd;
    reinterpret_cast<float4*>(g_aggx + (size_t)i * FF)[c] = v;
}

// one thread per (edge, float4-chunk): 8 chunks cover 32 raw features.
__global__ void k_scatter(const float* __restrict__ x,
                          const int* __restrict__ src, const int* __restrict__ dst) {
    unsigned idx = blockIdx.x * blockDim.x + threadIdx.x;
    if (idx >= (unsigned)EE * 8u) return;
    unsigned e = idx >> 3;
    unsigned c = idx & 7u;
    int s = __ldg(src + e);
    int d = __ldg(dst + e);
    float nrm = __ldg(&g_dinv[s]) * __ldg(&g_dinv[d]);
    float4 v = __ldg(reinterpret_cast<const float4*>(x + (size_t)s * FF) + c);
    v.x *= nrm; v.y *= nrm; v.z *= nrm; v.w *= nrm;
    float4* ap = reinterpret_cast<float4*>(g_aggx + (size_t)d * FF) + c;
    asm volatile("red.global.add.v4.f32 [%0], {%1,%2,%3,%4};"
                 :: "l"(ap), "f"(v.x), "f"(v.y), "f"(v.z), "f"(v.w) : "memory");
}

// one-time weight fold: Mt[g] = (W_g @ L_g[0:64])^T, Lbt[g] = L_g[64:128]^T,
// bv[g] = b_g @ L_g[0:64] + Lb_g.  One block, 192 threads active.
__global__ void k_prep(const float* __restrict__ Wz, const float* __restrict__ bz,
                       const float* __restrict__ Wr, const float* __restrict__ br,
                       const float* __restrict__ Wh, const float* __restrict__ bh,
                       const float* __restrict__ Lz, const float* __restrict__ Lzb,
                       const float* __restrict__ Lr, const float* __restrict__ Lrb,
                       const float* __restrict__ Lh, const float* __restrict__ Lhb) {
    int t = threadIdx.x;
    if (t >= 192) return;
    int g = t >> 6, j = t & 63;
    const float* W  = (g == 0) ? Wz  : (g == 1) ? Wr  : Wh;
    const float* b  = (g == 0) ? bz  : (g == 1) ? br  : bh;
    const float* L  = (g == 0) ? Lz  : (g == 1) ? Lr  : Lh;
    const float* Lb = (g == 0) ? Lzb : (g == 1) ? Lrb : Lhb;

    for (int f = 0; f < FF; f++) {
        float s = 0.f;
        for (int m = 0; m < HH; m++) s += W[f * HH + m] * L[m * HH + j];
        g_Mt[g][j][f] = s;
    }
    float sb = Lb[j];
    for (int m = 0; m < HH; m++) sb += b[m] * L[m * HH + j];
    g_bv[g][j] = sb;
    for (int k = 0; k < HH; k++) g_Lbt[g][j][k] = L[(HH + k) * HH + j];
}

// fused GCN-projection + GRU gates. Block = 256 threads = 8 warps = 64 nodes.
// Warp handles 8 nodes; lane owns output columns j0=lane, j1=lane+32.
__global__ void __launch_bounds__(256) k_gates2() {
    __shared__ float ag_sh[FF][SPAD];   // k-major staged aggx
    __shared__ float h_sh [HH][SPAD];   // k-major staged h
    __shared__ float hr_sh[HH][SPAD];   // k-major h*R

    int tid = threadIdx.x;
    int block_base = blockIdx.x * 64;

    // stage aggx: 64 nodes x 32 floats = 512 float4 -> 2 per thread
    #pragma unroll
    for (int r = 0; r < 2; r++) {
        int idx = r * 256 + tid;           // 0..511
        int n = idx >> 3, k4 = idx & 7;
        int node = block_base + n;
        float4 v = make_float4(0.f, 0.f, 0.f, 0.f);
        if (node < NN) v = __ldg(reinterpret_cast<const float4*>(g_aggx + (size_t)node * FF) + k4);
        ag_sh[k4 * 4 + 0][n] = v.x;
        ag_sh[k4 * 4 + 1][n] = v.y;
        ag_sh[k4 * 4 + 2][n] = v.z;
        ag_sh[k4 * 4 + 3][n] = v.w;
    }
    // stage h: 64 nodes x 64 floats = 1024 float4 -> 4 per thread
    #pragma unroll
    for (int r = 0; r < 4; r++) {
        int idx = r * 256 + tid;           // 0..1023
        int n = idx >> 4, k4 = idx & 15;
        int node = block_base + n;
        float4 v = make_float4(0.f, 0.f, 0.f, 0.f);
        if (node < NN) v = __ldg(reinterpret_cast<const float4*>(g_h + (size_t)node * HH) + k4);
        h_sh[k4 * 4 + 0][n] = v.x;
        h_sh[k4 * 4 + 1][n] = v.y;
        h_sh[k4 * 4 + 2][n] = v.z;
        h_sh[k4 * 4 + 3][n] = v.w;
    }
    __syncthreads();

    int warp = tid >> 5, lane = tid & 31;
    int nb = warp * 8;                     // node offset within block
    int j0 = lane, j1 = lane + 32;

    // ---- z & r gates -------------------------------------------------------
    float az0[8], az1[8], ar0[8], ar1[8];
    #pragma unroll
    for (int n = 0; n < 8; n++) { az0[n] = az1[n] = ar0[n] = ar1[n] = 0.f; }

    // top half: aggx (F=32) with folded weights Mt
    #pragma unroll
    for (int k4 = 0; k4 < FF / 4; k4++) {
        float4 wz0 = __ldg(reinterpret_cast<const float4*>(&g_Mt[0][j0][0]) + k4);
        float4 wz1 = __ldg(reinterpret_cast<const float4*>(&g_Mt[0][j1][0]) + k4);
        float4 wr0 = __ldg(reinterpret_cast<const float4*>(&g_Mt[1][j0][0]) + k4);
        float4 wr1 = __ldg(reinterpret_cast<const float4*>(&g_Mt[1][j1][0]) + k4);
        const float* pz0 = (const float*)&wz0; const float* pz1 = (const float*)&wz1;
        const float* pr0 = (const float*)&wr0; const float* pr1 = (const float*)&wr1;
        #pragma unroll
        for (int i = 0; i < 4; i++) {
            int k = k4 * 4 + i;
            float4 a0 = *reinterpret_cast<const float4*>(&ag_sh[k][nb]);
            float4 a1 = *reinterpret_cast<const float4*>(&ag_sh[k][nb + 4]);
            float aa[8] = {a0.x, a0.y, a0.z, a0.w, a1.x, a1.y, a1.z, a1.w};
            #pragma unroll
            for (int n = 0; n < 8; n++) {
                az0[n] = fmaf(aa[n], pz0[i], az0[n]);
                az1[n] = fmaf(aa[n], pz1[i], az1[n]);
                ar0[n] = fmaf(aa[n], pr0[i], ar0[n]);
                ar1[n] = fmaf(aa[n], pr1[i], ar1[n]);
            }
        }
    }
    // bottom half: h (K=64) with Lbt
    #pragma unroll
    for (int k4 = 0; k4 < HH / 4; k4++) {
        float4 wz0 = __ldg(reinterpret_cast<const float4*>(&g_Lbt[0][j0][0]) + k4);
        float4 wz1 = __ldg(reinterpret_cast<const float4*>(&g_Lbt[0][j1][0]) + k4);
        float4 wr0 = __ldg(reinterpret_cast<const float4*>(&g_Lbt[1][j0][0]) + k4);
        float4 wr1 = __ldg(reinterpret_cast<const float4*>(&g_Lbt[1][j1][0]) + k4);
        const float* pz0 = (const float*)&wz0; const float* pz1 = (const float*)&wz1;
        const float* pr0 = (const float*)&wr0; const float* pr1 = (const float*)&wr1;
        #pragma unroll
        for (int i = 0; i < 4; i++) {
            int k = k4 * 4 + i;
            float4 a0 = *reinterpret_cast<const float4*>(&h_sh[k][nb]);
            float4 a1 = *reinterpret_cast<const float4*>(&h_sh[k][nb + 4]);
            float aa[8] = {a0.x, a0.y, a0.z, a0.w, a1.x, a1.y, a1.z, a1.w};
            #pragma unroll
            for (int n = 0; n < 8; n++) {
                az0[n] = fmaf(aa[n], pz0[i], az0[n]);
                az1[n] = fmaf(aa[n], pz1[i], az1[n]);
                ar0[n] = fmaf(aa[n], pr0[i], ar0[n]);
                ar1[n] = fmaf(aa[n], pr1[i], ar1[n]);
            }
        }
    }

    float bvz0 = __ldg(&g_bv[0][j0]), bvz1 = __ldg(&g_bv[0][j1]);
    float bvr0 = __ldg(&g_bv[1][j0]), bvr1 = __ldg(&g_bv[1][j1]);

    float Z0a[8], Z1a[8];
    #pragma unroll
    for (int n = 0; n < 8; n++) {
        Z0a[n] = sigmoidf_(az0[n] + bvz0);
        Z1a[n] = sigmoidf_(az1[n] + bvz1);
        float R0 = sigmoidf_(ar0[n] + bvr0);
        float R1 = sigmoidf_(ar1[n] + bvr1);
        hr_sh[j0][nb + n] = h_sh[j0][nb + n] * R0;
        hr_sh[j1][nb + n] = h_sh[j1][nb + n] * R1;
    }
    __syncwarp();

    // ---- h gate ------------------------------------------------------------
    float ah0[8], ah1[8];
    #pragma unroll
    for (int n = 0; n < 8; n++) { ah0[n] = ah1[n] = 0.f; }

    #pragma unroll
    for (int k4 = 0; k4 < FF / 4; k4++) {
        float4 wh0 = __ldg(reinterpret_cast<const float4*>(&g_Mt[2][j0][0]) + k4);
        float4 wh1 = __ldg(reinterpret_cast<const float4*>(&g_Mt[2][j1][0]) + k4);
        const float* p0 = (const float*)&wh0; const float* p1 = (const float*)&wh1;
        #pragma unroll
        for (int i = 0; i < 4; i++) {
            int k = k4 * 4 + i;
            float4 a0 = *reinterpret_cast<const float4*>(&ag_sh[k][nb]);
            float4 a1 = *reinterpret_cast<const float4*>(&ag_sh[k][nb + 4]);
            float aa[8] = {a0.x, a0.y, a0.z, a0.w, a1.x, a1.y, a1.z, a1.w};
            #pragma unroll
            for (int n = 0; n < 8; n++) {
                ah0[n] = fmaf(aa[n], p0[i], ah0[n]);
                ah1[n] = fmaf(aa[n], p1[i], ah1[n]);
            }
        }
    }
    #pragma unroll
    for (int k4 = 0; k4 < HH / 4; k4++) {
        float4 wh0 = __ldg(reinterpret_cast<const float4*>(&g_Lbt[2][j0][0]) + k4);
        float4 wh1 = __ldg(reinterpret_cast<const float4*>(&g_Lbt[2][j1][0]) + k4);
        const float* p0 = (const float*)&wh0; const float* p1 = (const float*)&wh1;
        #pragma unroll
        for (int i = 0; i < 4; i++) {
            int k = k4 * 4 + i;
            float4 a0 = *reinterpret_cast<const float4*>(&hr_sh[k][nb]);
            float4 a1 = *reinterpret_cast<const float4*>(&hr_sh[k][nb + 4]);
            float aa[8] = {a0.x, a0.y, a0.z, a0.w, a1.x, a1.y, a1.z, a1.w};
            #pragma unroll
            for (int n = 0; n < 8; n++) {
                ah0[n] = fmaf(aa[n], p0[i], ah0[n]);
                ah1[n] = fmaf(aa[n], p1[i], ah1[n]);
            }
        }
    }

    float bvh0 = __ldg(&g_bv[2][j0]), bvh1 = __ldg(&g_bv[2][j1]);
    #pragma unroll
    for (int n = 0; n < 8; n++) {
        int node = block_base + nb + n;
        if (node < NN) {
            float Ht0 = tanhf(ah0[n] + bvh0);
            float Ht1 = tanhf(ah1[n] + bvh1);
            float h0 = h_sh[j0][nb + n];
            float h1 = h_sh[j1][nb + n];
            g_h[(size_t)node * HH + j0] = Z0a[n] * h0 + (1.f - Z0a[n]) * Ht0;
            g_h[(size_t)node * HH + j1] = Z1a[n] * h1 + (1.f - Z1a[n]) * Ht1;
        }
    }
}

__global__ void k_out(const float* __restrict__ oW, const float* __restrict__ ob,
                      float* __restrict__ out) {
    unsigned idx = blockIdx.x * blockDim.x + threadIdx.x;
    if (idx >= (unsigned)(NN * OUTC)) return;
    int i = idx >> 4, j = idx & 15;
    const float* hr = g_h + (size_t)i * HH;
    float acc = __ldg(ob + j);
    #pragma unroll
    for (int k = 0; k < HH; k++) acc += hr[k] * __ldg(oW + k * OUTC + j);
    out[idx] = acc;
}

// ---------------- launch ----------------------------------------------------
extern "C" void kernel_launch(void* const* d_in, const int* in_sizes, int n_in,
                              void* d_out, int out_size) {
    const float* xs  = (const float*)d_in[0];
    const int*   ei  = (const int*)  d_in[1];
    const float* Wz  = (const float*)d_in[2];
    const float* bz  = (const float*)d_in[3];
    const float* Wr  = (const float*)d_in[4];
    const float* br  = (const float*)d_in[5];
    const float* Wh  = (const float*)d_in[6];
    const float* bh  = (const float*)d_in[7];
    const float* Lz  = (const float*)d_in[8];
    const float* Lzb = (const float*)d_in[9];
    const float* Lr  = (const float*)d_in[10];
    const float* Lrb = (const float*)d_in[11];
    const float* Lh  = (const float*)d_in[12];
    const float* Lhb = (const float*)d_in[13];
    const float* oW  = (const float*)d_in[14];
    const float* ob  = (const float*)d_in[15];
    float* out = (float*)d_out;

    k_prep<<<1, 256>>>(Wz, bz, Wr, br, Wh, bh, Lz, Lzb, Lr, Lrb, Lh, Lhb);
    k_clear_h<<<(NN * HH + 255) / 256, 256>>>();

    for (int t = 0; t < TT; t++) {
        const float* x   = xs + (size_t)t * NN * FF;
        const int*   src = ei + (size_t)t * 2 * EE;
        const int*   dst = src + EE;

        k_clear_deg<<<(NN + 255) / 256, 256>>>();
        k_deg<<<(EE + 255) / 256, 256>>>(dst);
        k_init<<<(NN * 8 + 255) / 256, 256>>>(x);
        k_scatter<<<((unsigned)EE * 8u + 255) / 256, 256>>>(x, src, dst);
        k_gates2<<<(NN + 63) / 64, 256>>>();
    }

    k_out<<<(NN * OUTC + 255) / 256, 256>>>(oW, ob, out);
}